// round 17
// baseline (speedup 1.0000x reference)
#include <cuda_runtime.h>
#include <cstdint>

#define N_ENTITIES 100000
#define N_USERS    50000
#define N_FACTORS  4
#define N_RELATIONS 32
#define N_REL_USED 31
#define N_META     8
#define CHANNEL    64
#define N_EDGES    1600000
#define NNZ_CNT    1000000

#define SLOT   96                           // edge slots per head (Poisson 16)
#define SLOT_U 64                           // nnz slots per user (Poisson 20)

// ---- K1 split ----
#define BINE_B  280                         // bin edges by head
#define BINU_B  140                         // bin nnz by user
#define ATT_B   888                         // attention table (latency-bound)
#define K1_BLOCKS (BINE_B + BINU_B + ATT_B + 1)   // +1 disen

#define TILE_E 64
#define ATT_TILES ((N_ENTITIES + TILE_E - 1) / TILE_E)

// ---- K2 split ----
#define GATHE_B 740                         // edge gather
#define GATHU_B 444                         // user gather + blend
#define K2_BLOCKS (GATHE_B + GATHU_B)

// ------------------------- device-global scratch ---------------------------
// cursor contract: zero at kernel_launch entry (zero-init at module load;
// reset by K2 after consumption) -> deterministic on every call.
__device__ int   g_ecnt[N_ENTITIES];                   // per-head cursor/degree
__device__ int   g_ucnt[N_USERS];                      // per-user cursor/degree
__device__ int2  g_slot [(size_t)N_ENTITIES * SLOT];   // {tail, rel}
__device__ int2  g_uslot[(size_t)N_USERS * SLOT_U];    // {col, bits(val)}
__device__ float g_disen[N_FACTORS * CHANNEL];
__device__ float g_att[N_ENTITIES * N_REL_USED];       // sigmoid(ent[h].rel[r])

// ---------------------------------------------------------------------------
// K1: bin edges | bin nnz | att table | disen
// ---------------------------------------------------------------------------
__global__ void __launch_bounds__(256)
k1_kernel(const float* __restrict__ ent,
          const int*   __restrict__ head,
          const int*   __restrict__ tail,
          const int*   __restrict__ etype,
          const int*   __restrict__ mrow,
          const int*   __restrict__ mcol,
          const float* __restrict__ mval,
          const float* __restrict__ relw,
          const float* __restrict__ datt,
          const float* __restrict__ weight) {
    int b = blockIdx.x;

    if (b < BINE_B) {
        // ---- bin edges: thread per edge, fixed-slot cursor ----
        int t0      = b * 256 + threadIdx.x;
        int tstride = BINE_B * 256;
        for (int e = t0; e < N_EDGES; e += tstride) {
            int h = __ldg(&head[e]);
            int pos = atomicAdd(&g_ecnt[h], 1);
            g_slot[(size_t)h * SLOT + pos] =
                make_int2(__ldg(&tail[e]), __ldg(&etype[e]) - 1);
        }

    } else if (b < BINE_B + BINU_B) {
        // ---- bin nnz by user ----
        int t0      = (b - BINE_B) * 256 + threadIdx.x;
        int tstride = BINU_B * 256;
        for (int i = t0; i < NNZ_CNT; i += tstride) {
            int r = __ldg(&mrow[i]);
            int pos = atomicAdd(&g_ucnt[r], 1);
            g_uslot[(size_t)r * SLOT_U + pos] =
                make_int2(__ldg(&mcol[i]), __float_as_int(__ldg(&mval[i])));
        }

    } else if (b < BINE_B + BINU_B + ATT_B) {
        // ---- attention table: tile staging, 2-pass channel split ----
        __shared__ float s_ent[TILE_E * CHANNEL];     // 16 KB tile
        int lane = threadIdx.x & 31;
        int wid  = threadIdx.x >> 5;
        bool has_rel = (lane < N_REL_USED);
        const float4* rw = (const float4*)&relw[(has_rel ? lane : 0) * CHANNEL];

        int tile0 = b - (BINE_B + BINU_B);
        for (int tile = tile0; tile < ATT_TILES; tile += ATT_B) {
            int base = tile * TILE_E;
            int cnt  = min(TILE_E, N_ENTITIES - base);

            __syncthreads();
            const float4* src = (const float4*)&ent[(size_t)base * CHANNEL];
            for (int i = threadIdx.x; i < cnt * (CHANNEL / 4); i += 256)
                ((float4*)s_ent)[i] = __ldg(&src[i]);
            __syncthreads();

            float part[8];
            float4 rrel[8];

            #pragma unroll
            for (int i = 0; i < 8; i++)
                rrel[i] = has_rel ? __ldg(&rw[i]) : make_float4(0.f, 0.f, 0.f, 0.f);
            #pragma unroll
            for (int k8 = 0; k8 < 8; k8++) {
                int k = wid + k8 * 8;
                const float4* row = (const float4*)&s_ent[k * CHANNEL];
                float d0 = 0.f, d1 = 0.f;
                #pragma unroll
                for (int i = 0; i < 8; i++) {
                    float4 a = row[i];
                    d0 += a.x * rrel[i].x + a.z * rrel[i].z;
                    d1 += a.y * rrel[i].y + a.w * rrel[i].w;
                }
                part[k8] = d0 + d1;
            }

            #pragma unroll
            for (int i = 0; i < 8; i++)
                rrel[i] = has_rel ? __ldg(&rw[8 + i]) : make_float4(0.f, 0.f, 0.f, 0.f);
            #pragma unroll
            for (int k8 = 0; k8 < 8; k8++) {
                int k = wid + k8 * 8;
                const float4* row = (const float4*)&s_ent[k * CHANNEL + 32];
                float d0 = 0.f, d1 = 0.f;
                #pragma unroll
                for (int i = 0; i < 8; i++) {
                    float4 a = row[i];
                    d0 += a.x * rrel[i].x + a.z * rrel[i].z;
                    d1 += a.y * rrel[i].y + a.w * rrel[i].w;
                }
                float d = part[k8] + d0 + d1;
                if (has_rel && k < cnt)
                    g_att[(size_t)(base + k) * N_REL_USED + lane] =
                        1.0f / (1.0f + __expf(-d));
            }
        }

    } else {
        // ---- disen_weight = softmax(disen_weight_att, -1) @ weight ----
        int c = threadIdx.x;
        if (c >= CHANNEL) return;
        #pragma unroll
        for (int f = 0; f < N_FACTORS; f++) {
            float a[N_META];
            float m = -1e30f;
            #pragma unroll
            for (int j = 0; j < N_META; j++) { a[j] = datt[f * N_META + j]; m = fmaxf(m, a[j]); }
            float s = 0.0f;
            #pragma unroll
            for (int j = 0; j < N_META; j++) { a[j] = __expf(a[j] - m); s += a[j]; }
            float inv = 1.0f / s;
            float acc = 0.0f;
            #pragma unroll
            for (int j = 0; j < N_META; j++) acc += a[j] * inv * weight[j * CHANNEL + c];
            g_disen[f * CHANNEL + c] = acc;
        }
    }
}

// ---------------------------------------------------------------------------
// K2: edge gather | user gather + blend.
//     int4 PAIR loads: each half-warp processes item-pairs (2 payloads per
//     16B LDG, 2 independent row loads in flight). Plain stores, fused
//     mean / softmax-blend. Cursors reset after consumption.
// ---------------------------------------------------------------------------
__global__ void __launch_bounds__(256)
k2_kernel(const float* __restrict__ ent,
          const float* __restrict__ user_emb,
          const float* __restrict__ latent,
          const float* __restrict__ relw,
          float* __restrict__ out_ent,
          float* __restrict__ out_user) {
    int lane = threadIdx.x & 31;
    int li   = lane & 15;
    int half = lane >> 4;

    if (blockIdx.x < GATHE_B) {
        // ---------------- edge gather ----------------
        __shared__ float s_rel[N_REL_USED * CHANNEL];
        for (int i = threadIdx.x; i < N_REL_USED * CHANNEL; i += blockDim.x)
            s_rel[i] = relw[i];
        __syncthreads();

        int w      = blockIdx.x * 8 + (threadIdx.x >> 5);
        int stride = GATHE_B * 8;

        for (int h = w; h < N_ENTITIES; h += stride) {
            int deg = __ldg(&g_ecnt[h]);
            const int4*  slot4 = (const int4*)&g_slot[(size_t)h * SLOT];
            const float* arow  = &g_att[(size_t)h * N_REL_USED];

            float4 acc = make_float4(0.f, 0.f, 0.f, 0.f);
            // pair p covers items 2p, 2p+1; halves alternate pairs
            for (int p = half; p * 2 < deg; p += 2) {
                int4 q = __ldg(&slot4[p]);
                // item A
                float  attA = __ldg(&arow[q.y]);
                float4 etA  = __ldg((const float4*)&ent[(size_t)q.x * CHANNEL + li * 4]);
                float4 rlA  = *(const float4*)&s_rel[q.y * CHANNEL + li * 4];
                // item B (may be out of range on last odd pair)
                bool hasB = (p * 2 + 1 < deg);
                float  attB = hasB ? __ldg(&arow[q.w]) : 0.0f;
                float4 etB  = hasB ? __ldg((const float4*)&ent[(size_t)q.z * CHANNEL + li * 4])
                                   : make_float4(0.f, 0.f, 0.f, 0.f);
                float4 rlB  = hasB ? *(const float4*)&s_rel[q.w * CHANNEL + li * 4]
                                   : make_float4(0.f, 0.f, 0.f, 0.f);

                acc.x += attA * etA.x * rlA.x + attB * etB.x * rlB.x;
                acc.y += attA * etA.y * rlA.y + attB * etB.y * rlB.y;
                acc.z += attA * etA.z * rlA.z + attB * etB.z * rlB.z;
                acc.w += attA * etA.w * rlA.w + attB * etB.w * rlB.w;
            }
            acc.x += __shfl_xor_sync(0xFFFFFFFFu, acc.x, 16);
            acc.y += __shfl_xor_sync(0xFFFFFFFFu, acc.y, 16);
            acc.z += __shfl_xor_sync(0xFFFFFFFFu, acc.z, 16);
            acc.w += __shfl_xor_sync(0xFFFFFFFFu, acc.w, 16);

            if (half == 0) {
                float inv = 1.0f / fmaxf((float)deg, 1.0f);
                float4* o = (float4*)&out_ent[(size_t)h * CHANNEL + li * 4];
                *o = make_float4(acc.x * inv, acc.y * inv, acc.z * inv, acc.w * inv);
            }
            if (lane == 0) g_ecnt[h] = 0;      // reset after consumption
        }
    } else {
        // ---------------- user gather + softmax blend ----------------
        __shared__ float s_lat[N_FACTORS * CHANNEL];
        __shared__ float s_dis[N_FACTORS * CHANNEL];
        for (int i = threadIdx.x; i < N_FACTORS * CHANNEL; i += blockDim.x) {
            s_lat[i] = latent[i];
            s_dis[i] = g_disen[i];
        }
        __syncthreads();

        int w      = (blockIdx.x - GATHE_B) * 8 + (threadIdx.x >> 5);
        int stride = GATHU_B * 8;

        for (int u = w; u < N_USERS; u += stride) {
            int deg = __ldg(&g_ucnt[u]);
            const int4* slot4 = (const int4*)&g_uslot[(size_t)u * SLOT_U];

            float4 acc = make_float4(0.f, 0.f, 0.f, 0.f);
            for (int p = half; p * 2 < deg; p += 2) {
                int4 q = __ldg(&slot4[p]);
                float  vA = __int_as_float(q.y);
                float4 eA = __ldg((const float4*)&ent[(size_t)q.x * CHANNEL + li * 4]);
                bool hasB = (p * 2 + 1 < deg);
                float  vB = hasB ? __int_as_float(q.w) : 0.0f;
                float4 eB = hasB ? __ldg((const float4*)&ent[(size_t)q.z * CHANNEL + li * 4])
                                 : make_float4(0.f, 0.f, 0.f, 0.f);
                acc.x += vA * eA.x + vB * eB.x;
                acc.y += vA * eA.y + vB * eB.y;
                acc.z += vA * eA.z + vB * eB.z;
                acc.w += vA * eA.w + vB * eB.w;
            }
            acc.x += __shfl_xor_sync(0xFFFFFFFFu, acc.x, 16);
            acc.y += __shfl_xor_sync(0xFFFFFFFFu, acc.y, 16);
            acc.z += __shfl_xor_sync(0xFFFFFFFFu, acc.z, 16);
            acc.w += __shfl_xor_sync(0xFFFFFFFFu, acc.w, 16);

            // score softmax: each 16-lane half holds the full row (li*4)
            float4 ue = __ldg((const float4*)&user_emb[(size_t)u * CHANNEL + li * 4]);
            float s[N_FACTORS];
            #pragma unroll
            for (int f = 0; f < N_FACTORS; f++) {
                const float4 lt = *(const float4*)&s_lat[f * CHANNEL + li * 4];
                float d = ue.x * lt.x + ue.y * lt.y + ue.z * lt.z + ue.w * lt.w;
                #pragma unroll
                for (int o = 8; o > 0; o >>= 1)
                    d += __shfl_xor_sync(0xFFFFFFFFu, d, o);
                s[f] = d;
            }
            float m = fmaxf(fmaxf(s[0], s[1]), fmaxf(s[2], s[3]));
            float sum = 0.0f;
            #pragma unroll
            for (int f = 0; f < N_FACTORS; f++) { s[f] = __expf(s[f] - m); sum += s[f]; }
            float inv = 1.0f / sum;

            float4 c = make_float4(0.f, 0.f, 0.f, 0.f);
            #pragma unroll
            for (int f = 0; f < N_FACTORS; f++) {
                float sc = s[f] * inv;
                const float4 dw = *(const float4*)&s_dis[f * CHANNEL + li * 4];
                c.x += sc * dw.x;
                c.y += sc * dw.y;
                c.z += sc * dw.z;
                c.w += sc * dw.w;
            }

            if (half == 0) {
                float4* o = (float4*)&out_user[(size_t)u * CHANNEL + li * 4];
                *o = make_float4(acc.x * (1.0f + c.x), acc.y * (1.0f + c.y),
                                 acc.z * (1.0f + c.z), acc.w * (1.0f + c.w));
            }
            if (lane == 0) g_ucnt[u] = 0;      // reset after consumption
        }
    }
}

// ---------------------------------------------------------------------------
extern "C" void kernel_launch(void* const* d_in, const int* in_sizes, int n_in,
                              void* d_out, int out_size)
{
    const float* entity_emb = (const float*)d_in[0];
    const float* user_emb   = (const float*)d_in[1];
    const float* latent_emb = (const float*)d_in[2];
    const int*   head       = (const int*)d_in[3];
    const int*   tail       = (const int*)d_in[4];
    const int*   edge_type  = (const int*)d_in[5];
    const int*   mat_row    = (const int*)d_in[6];
    const int*   mat_col    = (const int*)d_in[7];
    const float* mat_val    = (const float*)d_in[8];
    const float* rel_w      = (const float*)d_in[9];
    const float* weight     = (const float*)d_in[10];
    const float* disen_att  = (const float*)d_in[11];

    float* out      = (float*)d_out;
    float* out_ent  = out;                                 // (N_ENTITIES, 64)
    float* out_user = out + (size_t)N_ENTITIES * CHANNEL;  // (N_USERS, 64)

    k1_kernel<<<K1_BLOCKS, 256>>>(entity_emb, head, tail, edge_type,
                                  mat_row, mat_col, mat_val,
                                  rel_w, disen_att, weight);

    k2_kernel<<<K2_BLOCKS, 256>>>(entity_emb, user_emb, latent_emb,
                                  rel_w, out_ent, out_user);
}